// round 3
// baseline (speedup 1.0000x reference)
#include <cuda_runtime.h>
#include <cstdint>

// Problem constants (fixed by the reference: N=200000, D=128, K=512)
#define DD 128
#define KK 512
#define NMAX 200000
#define PARTS 4

// GEMM tiling for the assign kernel
#define BM 128   // points per block
#define BN 128   // centers per tile
#define BK 16    // d-chunk
#define TM 8
#define TN 8

// ---------------- scratch (no allocations allowed) ----------------
__device__ int   g_assign[NMAX];
__device__ float g_c2[KK];
__device__ float g_sums[PARTS * KK * DD];
__device__ int   g_counts[KK];

// ---------------- init: zero accumulators + compute c2 ----------------
__global__ void init_kernel(const float* __restrict__ C) {
    int t = blockIdx.x * blockDim.x + threadIdx.x;
    if (t < PARTS * KK * DD) g_sums[t] = 0.0f;
    if (t < KK) {
        g_counts[t] = 0;
        const float* row = C + t * DD;
        float s = 0.0f;
        #pragma unroll 8
        for (int d = 0; d < DD; ++d) { float v = row[d]; s += v * v; }
        g_c2[t] = s;
    }
}

// ---------------- assign: fused distance GEMM + argmin ----------------
__global__ __launch_bounds__(256, 2)
void assign_kernel(const float* __restrict__ F,
                   const float* __restrict__ C,
                   int N,
                   float* __restrict__ out_assign) {
    __shared__ float sF[BK][BM + 4];
    __shared__ float sC[BK][BN + 4];
    __shared__ float sc2[BN];

    const int tid = threadIdx.x;
    const int tx = tid & 15;      // center sub-column (0..15)
    const int ty = tid >> 4;      // point sub-row   (0..15)
    const int pbase = blockIdx.x * BM;

    float best[TM];
    int   bidx[TM];
    #pragma unroll
    for (int i = 0; i < TM; ++i) { best[i] = 3.4e38f; bidx[i] = 0; }

    for (int tile = 0; tile < KK / BN; ++tile) {
        __syncthreads();  // guard smem reuse across tiles
        if (tid < BN) sc2[tid] = g_c2[tile * BN + tid];

        float acc[TM][TN];
        #pragma unroll
        for (int i = 0; i < TM; ++i)
            #pragma unroll
            for (int j = 0; j < TN; ++j) acc[i][j] = 0.0f;

        for (int d0 = 0; d0 < DD; d0 += BK) {
            // cooperative loads: 2048 floats each for F-tile and C-tile
            #pragma unroll
            for (int r = 0; r < 2; ++r) {
                int idx = tid + r * 256;        // 0..511 float4 slots
                int m  = idx >> 2;              // 0..127
                int dq = (idx & 3) << 2;        // 0,4,8,12
                int p  = pbase + m;
                float4 v = make_float4(0.f, 0.f, 0.f, 0.f);
                if (p < N)
                    v = *reinterpret_cast<const float4*>(F + (size_t)p * DD + d0 + dq);
                sF[dq + 0][m] = v.x; sF[dq + 1][m] = v.y;
                sF[dq + 2][m] = v.z; sF[dq + 3][m] = v.w;

                float4 w = *reinterpret_cast<const float4*>(
                    C + (size_t)(tile * BN + m) * DD + d0 + dq);
                sC[dq + 0][m] = w.x; sC[dq + 1][m] = w.y;
                sC[dq + 2][m] = w.z; sC[dq + 3][m] = w.w;
            }
            __syncthreads();

            #pragma unroll
            for (int d = 0; d < BK; ++d) {
                float4 a0 = *reinterpret_cast<const float4*>(&sF[d][ty * TM]);
                float4 a1 = *reinterpret_cast<const float4*>(&sF[d][ty * TM + 4]);
                float4 b0 = *reinterpret_cast<const float4*>(&sC[d][tx * TN]);
                float4 b1 = *reinterpret_cast<const float4*>(&sC[d][tx * TN + 4]);
                float rA[TM] = {a0.x, a0.y, a0.z, a0.w, a1.x, a1.y, a1.z, a1.w};
                float rB[TN] = {b0.x, b0.y, b0.z, b0.w, b1.x, b1.y, b1.z, b1.w};
                #pragma unroll
                for (int i = 0; i < TM; ++i)
                    #pragma unroll
                    for (int j = 0; j < TN; ++j)
                        acc[i][j] += rA[i] * rB[j];
            }
            __syncthreads();
        }

        // epilogue: d2' = c2 - 2*dot  (||x||^2 dropped: constant per point)
        #pragma unroll
        for (int i = 0; i < TM; ++i) {
            #pragma unroll
            for (int j = 0; j < TN; ++j) {
                int n = tx * TN + j;
                float d2 = fmaf(-2.0f, acc[i][j], sc2[n]);
                int gidx = tile * BN + n;
                if (d2 < best[i]) { best[i] = d2; bidx[i] = gidx; }
            }
        }
    }

    // reduce argmin across the 16 tx-threads sharing each point row
    #pragma unroll
    for (int i = 0; i < TM; ++i) {
        float bv = best[i];
        int   bi = bidx[i];
        #pragma unroll
        for (int off = 8; off > 0; off >>= 1) {
            float ov = __shfl_xor_sync(0xFFFFFFFFu, bv, off);
            int   oi = __shfl_xor_sync(0xFFFFFFFFu, bi, off);
            if (ov < bv || (ov == bv && oi < bi)) { bv = ov; bi = oi; }
        }
        if (tx == 0) {
            int p = pbase + ty * TM + i;
            if (p < N) {
                g_assign[p] = bi;
                if (out_assign) out_assign[p] = (float)bi;
            }
        }
    }
}

// ---------------- accumulate: one warp per point, privatized atomics ----------------
__global__ __launch_bounds__(256)
void accum_kernel(const float* __restrict__ F, int N) {
    int warp = (blockIdx.x * blockDim.x + threadIdx.x) >> 5;
    int lane = threadIdx.x & 31;
    if (warp >= N) return;
    int a = g_assign[warp];
    float4 v = reinterpret_cast<const float4*>(F + (size_t)warp * DD)[lane];
    float* dst = g_sums + (size_t)(blockIdx.x & (PARTS - 1)) * (KK * DD)
               + a * DD + lane * 4;
    atomicAdd(dst + 0, v.x);
    atomicAdd(dst + 1, v.y);
    atomicAdd(dst + 2, v.z);
    atomicAdd(dst + 3, v.w);
    if (lane == 0) atomicAdd(&g_counts[a], 1);
}

// ---------------- finalize: merge privatized copies, divide ----------------
__global__ void finalize_kernel(float* __restrict__ out) {
    int t = blockIdx.x * blockDim.x + threadIdx.x;
    if (t >= KK * DD) return;
    float s = 0.0f;
    #pragma unroll
    for (int p = 0; p < PARTS; ++p) s += g_sums[p * KK * DD + t];
    int k = t >> 7;  // /DD
    float c = fmaxf((float)g_counts[k], 1.0f);
    out[t] = s / c;
}

// ---------------- launch ----------------
extern "C" void kernel_launch(void* const* d_in, const int* in_sizes, int n_in,
                              void* d_out, int out_size) {
    const float* F = (const float*)d_in[0];
    const float* C = (const float*)d_in[1];
    // defensive: F is the big one
    if (n_in >= 2 && in_sizes[0] < in_sizes[1]) {
        const float* t = F; F = C; C = t;
        // sizes swap handled below by recomputing from the larger
    }
    int szF = in_sizes[0] > in_sizes[1] ? in_sizes[0] : in_sizes[1];
    int N = szF / DD;
    if (N > NMAX) N = NMAX;

    float* out = (float*)d_out;
    const int KD = KK * DD;
    float* out_assign = (out_size >= KD + N) ? (out + KD) : nullptr;

    init_kernel<<<(PARTS * KD + 255) / 256, 256>>>(C);
    assign_kernel<<<(N + BM - 1) / BM, 256>>>(F, C, N, out_assign);
    accum_kernel<<<(N + 7) / 8, 256>>>(F, N);
    finalize_kernel<<<(KD + 255) / 256, 256>>>(out);
}

// round 6
// speedup vs baseline: 1.0341x; 1.0341x over previous
#include <cuda_runtime.h>
#include <cstdint>

// Problem constants (fixed by the reference: N=200000, D=128, K=512)
#define DD 128
#define KK 512
#define NMAX 200000
#define PARTS 4

// GEMM tiling for the assign kernel
#define BM 128   // points per block
#define BN 128   // centers per tile
#define BK 16    // d-chunk
#define TM 8     // rows per thread
#define TN 8     // cols per thread (= 4 packed pairs)

// ---------------- scratch (no allocations allowed) ----------------
__device__ int   g_assign[NMAX];
__device__ float g_c2[KK];
__device__ float g_sums[PARTS * KK * DD];
__device__ int   g_counts[KK];

// ---------------- init: zero accumulators + compute c2 ----------------
__global__ void init_kernel(const float* __restrict__ C) {
    int t = blockIdx.x * blockDim.x + threadIdx.x;
    if (t < PARTS * KK * DD) g_sums[t] = 0.0f;
    if (t < KK) {
        g_counts[t] = 0;
        const float* row = C + t * DD;
        float s = 0.0f;
        #pragma unroll 8
        for (int d = 0; d < DD; ++d) { float v = row[d]; s += v * v; }
        g_c2[t] = s;
    }
}

__device__ __forceinline__ unsigned long long dup2(float x) {
    unsigned u = __float_as_uint(x);
    return (unsigned long long)u | ((unsigned long long)u << 32);
}

// ---------------- assign: f32x2 packed distance GEMM + fused argmin ----------------
__global__ __launch_bounds__(256, 2)
void assign_kernel(const float* __restrict__ F,
                   const float* __restrict__ C,
                   int N,
                   float* __restrict__ out_assign) {
    // F tile stored as duplicated pairs (a,a) so FFMA2 A-operand needs no dup movs
    __shared__ unsigned long long sFd[BK][BM + 2];   // +2 keeps 16B alignment per row
    __shared__ float sC[BK][BN + 4];
    __shared__ float sc2[BN];

    const int tid = threadIdx.x;
    const int tx = tid & 15;      // center sub-column (0..15)
    const int ty = tid >> 4;      // point sub-row   (0..15)
    const int pbase = blockIdx.x * BM;

    float best[TM];
    int   bidx[TM];
    #pragma unroll
    for (int i = 0; i < TM; ++i) { best[i] = 3.4e38f; bidx[i] = 0; }

    for (int tile = 0; tile < KK / BN; ++tile) {
        __syncthreads();  // guard smem reuse across tiles
        if (tid < BN) sc2[tid] = g_c2[tile * BN + tid];

        unsigned long long acc[TM][TN / 2];
        #pragma unroll
        for (int i = 0; i < TM; ++i)
            #pragma unroll
            for (int q = 0; q < TN / 2; ++q) acc[i][q] = 0ull;

        for (int d0 = 0; d0 < DD; d0 += BK) {
            // cooperative loads: 512 float4 slots each for F-tile and C-tile
            #pragma unroll
            for (int r = 0; r < 2; ++r) {
                int idx = tid + r * 256;        // 0..511
                int m  = idx >> 2;              // 0..127
                int dq = (idx & 3) << 2;        // 0,4,8,12
                int p  = pbase + m;
                float4 v = make_float4(0.f, 0.f, 0.f, 0.f);
                if (p < N)
                    v = *reinterpret_cast<const float4*>(F + (size_t)p * DD + d0 + dq);
                sFd[dq + 0][m] = dup2(v.x);
                sFd[dq + 1][m] = dup2(v.y);
                sFd[dq + 2][m] = dup2(v.z);
                sFd[dq + 3][m] = dup2(v.w);

                float4 w = *reinterpret_cast<const float4*>(
                    C + (size_t)(tile * BN + m) * DD + d0 + dq);
                sC[dq + 0][m] = w.x; sC[dq + 1][m] = w.y;
                sC[dq + 2][m] = w.z; sC[dq + 3][m] = w.w;
            }
            __syncthreads();

            #pragma unroll
            for (int d = 0; d < BK; ++d) {
                // A: 8 dup-pairs (one per row), warp-broadcast LDS.128 x4
                ulonglong2 a01 = *reinterpret_cast<const ulonglong2*>(&sFd[d][ty * TM + 0]);
                ulonglong2 a23 = *reinterpret_cast<const ulonglong2*>(&sFd[d][ty * TM + 2]);
                ulonglong2 a45 = *reinterpret_cast<const ulonglong2*>(&sFd[d][ty * TM + 4]);
                ulonglong2 a67 = *reinterpret_cast<const ulonglong2*>(&sFd[d][ty * TM + 6]);
                // B: 4 natural pairs (consecutive centers), LDS.128 x2
                ulonglong2 b01 = *reinterpret_cast<const ulonglong2*>(&sC[d][tx * TN]);
                ulonglong2 b23 = *reinterpret_cast<const ulonglong2*>(&sC[d][tx * TN + 4]);
                unsigned long long ap[TM] = {a01.x, a01.y, a23.x, a23.y,
                                             a45.x, a45.y, a67.x, a67.y};
                unsigned long long bp[TN / 2] = {b01.x, b01.y, b23.x, b23.y};
                #pragma unroll
                for (int i = 0; i < TM; ++i)
                    #pragma unroll
                    for (int q = 0; q < TN / 2; ++q)
                        asm("fma.rn.f32x2 %0, %1, %2, %0;"
                            : "+l"(acc[i][q]) : "l"(ap[i]), "l"(bp[q]));
            }
            __syncthreads();
        }

        // epilogue: d2' = c2 - 2*dot  (||x||^2 dropped: constant per point)
        #pragma unroll
        for (int i = 0; i < TM; ++i) {
            #pragma unroll
            for (int q = 0; q < TN / 2; ++q) {
                unsigned long long p = acc[i][q];
                float dlo = __uint_as_float((unsigned)p);
                float dhi = __uint_as_float((unsigned)(p >> 32));
                int n0 = tx * TN + q * 2;
                float e0 = fmaf(-2.0f, dlo, sc2[n0]);
                float e1 = fmaf(-2.0f, dhi, sc2[n0 + 1]);
                int g0 = tile * BN + n0;
                if (e0 < best[i]) { best[i] = e0; bidx[i] = g0; }
                if (e1 < best[i]) { best[i] = e1; bidx[i] = g0 + 1; }
            }
        }
    }

    // reduce argmin across the 16 tx-threads sharing each point row
    #pragma unroll
    for (int i = 0; i < TM; ++i) {
        float bv = best[i];
        int   bi = bidx[i];
        #pragma unroll
        for (int off = 8; off > 0; off >>= 1) {
            float ov = __shfl_xor_sync(0xFFFFFFFFu, bv, off);
            int   oi = __shfl_xor_sync(0xFFFFFFFFu, bi, off);
            if (ov < bv || (ov == bv && oi < bi)) { bv = ov; bi = oi; }
        }
        if (tx == 0) {
            int p = pbase + ty * TM + i;
            if (p < N) {
                g_assign[p] = bi;
                out_assign[p] = (float)bi;
            }
        }
    }
}

// ---------------- accumulate: warp/point, vector red.global.add.v4 ----------------
__global__ __launch_bounds__(256)
void accum_kernel(const float* __restrict__ F, int N) {
    int warp = (blockIdx.x * blockDim.x + threadIdx.x) >> 5;
    int lane = threadIdx.x & 31;
    if (warp >= N) return;
    int a = g_assign[warp];
    float4 v = reinterpret_cast<const float4*>(F + (size_t)warp * DD)[lane];
    float* dst = g_sums + (size_t)(warp & (PARTS - 1)) * (KK * DD) + a * DD + lane * 4;
    asm volatile("red.global.add.v4.f32 [%0], {%1, %2, %3, %4};"
                 :: "l"(dst), "f"(v.x), "f"(v.y), "f"(v.z), "f"(v.w) : "memory");
    if (lane == 0) atomicAdd(&g_counts[a], 1);
}

// ---------------- finalize: merge privatized copies, divide ----------------
__global__ void finalize_kernel(float* __restrict__ out) {
    int t = blockIdx.x * blockDim.x + threadIdx.x;
    if (t >= KK * DD) return;
    float s = 0.0f;
    #pragma unroll
    for (int p = 0; p < PARTS; ++p) s += g_sums[p * KK * DD + t];
    int k = t >> 7;  // /DD
    float c = fmaxf((float)g_counts[k], 1.0f);
    out[t] = s / c;
}

// ---------------- launch ----------------
extern "C" void kernel_launch(void* const* d_in, const int* in_sizes, int n_in,
                              void* d_out, int out_size) {
    const float* F = (const float*)d_in[0];
    const float* C = (const float*)d_in[1];
    if (n_in >= 2 && in_sizes[0] < in_sizes[1]) { const float* t = F; F = C; C = t; }
    int szF = in_sizes[0] > in_sizes[1] ? in_sizes[0] : in_sizes[1];
    int N = szF / DD;
    if (N > NMAX) N = NMAX;

    float* out = (float*)d_out;
    const int KD = KK * DD;
    float* out_assign = out + KD;  // harness sizes out as KD + N

    init_kernel<<<(PARTS * KD + 255) / 256, 256>>>(C);
    assign_kernel<<<(N + BM - 1) / BM, 256>>>(F, C, N, out_assign);
    accum_kernel<<<(N + 7) / 8, 256>>>(F, N);
    finalize_kernel<<<(KD + 255) / 256, 256>>>(out);
}

// round 8
// speedup vs baseline: 2.4916x; 2.4094x over previous
#include <cuda_runtime.h>
#include <cuda_fp16.h>
#include <cstdint>

// Problem constants (fixed by the reference: N=200000, D=128, K=512)
#define DD 128
#define KK 512
#define NMAX 200000
#define PARTS 4

#define BM 128            // points per CTA
#define RS 136            // padded smem row stride in fp16 elems (272B)
#define RSB 272           // row stride bytes
#define TILE_HB (128*RSB) // one 128x128 fp16 padded tile = 34816 B

// smem offsets (bytes)
#define SM_FH  0
#define SM_FL  (SM_FH + TILE_HB)
#define SM_CH  (SM_FL + TILE_HB)
#define SM_CL  (SM_CH + TILE_HB)
#define SM_C2  (SM_CL + TILE_HB)          // 512 floats
#define SM_MRG (SM_C2 + 2048)             // 2 x 128 (float,int)
#define SMEM_TOTAL (SM_MRG + 2048)

// ---------------- scratch (no allocations allowed) ----------------
__device__ int   g_assign[NMAX];
__device__ float g_c2[KK];
__device__ float g_sums[PARTS * KK * DD];
__device__ int   g_counts[KK];
// centers as hi/lo fp16 in padded tile layout: [4 tiles][128 rows][RS]
__device__ __align__(16) unsigned short g_chi[4 * 128 * RS];
__device__ __align__(16) unsigned short g_clo[4 * 128 * RS];

__device__ __forceinline__ unsigned smem_u32(const void* p) {
    unsigned a;
    asm("{ .reg .u64 t; cvta.to.shared.u64 t, %1; cvt.u32.u64 %0, t; }" : "=r"(a) : "l"(p));
    return a;
}

__device__ __forceinline__ void ldmx4(unsigned* r, unsigned addr) {
    asm volatile("ldmatrix.sync.aligned.m8n8.x4.shared.b16 {%0,%1,%2,%3}, [%4];"
                 : "=r"(r[0]), "=r"(r[1]), "=r"(r[2]), "=r"(r[3]) : "r"(addr));
}
__device__ __forceinline__ void mma16816(float* d, const unsigned* a, const unsigned* b) {
    asm volatile("mma.sync.aligned.m16n8k16.row.col.f32.f16.f16.f32 "
                 "{%0,%1,%2,%3}, {%4,%5,%6,%7}, {%8,%9}, {%0,%1,%2,%3};"
                 : "+f"(d[0]), "+f"(d[1]), "+f"(d[2]), "+f"(d[3])
                 : "r"(a[0]), "r"(a[1]), "r"(a[2]), "r"(a[3]), "r"(b[0]), "r"(b[1]));
}

// ---------------- prep: zero sums, c2, center hi/lo images ----------------
__global__ void prep_kernel(const float* __restrict__ C) {
    int t = blockIdx.x * blockDim.x + threadIdx.x;
    if (t < PARTS * KK * DD) g_sums[t] = 0.0f;
    if (t < KK * DD) {
        int c = t >> 7, k = t & 127;
        float x = C[t];
        __half hi = __float2half_rn(x);
        __half lo = __float2half_rn(x - __half2float(hi));
        int tile = c >> 7, r = c & 127;
        int idx = tile * (128 * RS) + r * RS + k;
        g_chi[idx] = __half_as_ushort(hi);
        g_clo[idx] = __half_as_ushort(lo);
    }
    if (t < KK) {
        g_counts[t] = 0;
        const float* row = C + t * DD;
        float s = 0.0f;
        #pragma unroll 8
        for (int d = 0; d < DD; ++d) { float v = row[d]; s += v * v; }
        g_c2[t] = s;
    }
}

// ---------------- assign: HMMA fp16-split distance GEMM + fused argmin ----------------
__global__ __launch_bounds__(256, 1)
void assign_kernel(const float* __restrict__ F, int N, float* __restrict__ out_assign) {
    extern __shared__ char smem[];
    const unsigned sbase = smem_u32(smem);
    const int tid = threadIdx.x;
    const int wid = tid >> 5;
    const int l = tid & 31;
    const int pbase = blockIdx.x * BM;

    const int warpM = (wid >> 1) * 32;     // point rows 0..96
    const int warpNh = wid & 1;            // n-half (0: cols 0-63, 1: 64-127)

    // ---- convert F block to hi/lo fp16 in padded smem ----
    #pragma unroll
    for (int it = 0; it < 16; ++it) {
        int s = tid + it * 256;            // 4096 float4 slots
        int row = s >> 5;                  // 0..127
        int q = s & 31;                    // float4 within row
        int p = pbase + row;
        float4 v = make_float4(0.f, 0.f, 0.f, 0.f);
        if (p < N) v = *reinterpret_cast<const float4*>(F + (size_t)p * DD + q * 4);
        __half h0 = __float2half_rn(v.x), h1 = __float2half_rn(v.y);
        __half h2 = __float2half_rn(v.z), h3 = __float2half_rn(v.w);
        __half l0 = __float2half_rn(v.x - __half2float(h0));
        __half l1 = __float2half_rn(v.y - __half2float(h1));
        __half l2 = __float2half_rn(v.z - __half2float(h2));
        __half l3 = __float2half_rn(v.w - __half2float(h3));
        unsigned hp0 = __half_as_ushort(h0) | ((unsigned)__half_as_ushort(h1) << 16);
        unsigned hp1 = __half_as_ushort(h2) | ((unsigned)__half_as_ushort(h3) << 16);
        unsigned lp0 = __half_as_ushort(l0) | ((unsigned)__half_as_ushort(l1) << 16);
        unsigned lp1 = __half_as_ushort(l2) | ((unsigned)__half_as_ushort(l3) << 16);
        int boff = row * RSB + q * 8;
        *reinterpret_cast<uint2*>(smem + SM_FH + boff) = make_uint2(hp0, hp1);
        *reinterpret_cast<uint2*>(smem + SM_FL + boff) = make_uint2(lp0, lp1);
    }
    // c2 -> smem
    ((float*)(smem + SM_C2))[tid]       = g_c2[tid];
    ((float*)(smem + SM_C2))[tid + 256] = g_c2[tid + 256];
    __syncthreads();

    // ldmatrix lane-relative offsets
    const unsigned aOff = (unsigned)((l & 15) * RSB + ((l >> 4) & 1) * 16);
    const unsigned bOff = (unsigned)((((l >> 4) & 1) * 8 + (l & 7)) * RSB + ((l >> 3) & 1) * 16);

    float best[4];
    int   bidx[4];
    #pragma unroll
    for (int j = 0; j < 4; ++j) { best[j] = 3.4e38f; bidx[j] = 0; }

    const float* sc2s = (const float*)(smem + SM_C2);

    #pragma unroll 1
    for (int nt = 0; nt < 4; ++nt) {
        // copy this center tile (hi+lo) into smem
        {
            const int4* srcH = reinterpret_cast<const int4*>(g_chi + nt * (128 * RS));
            const int4* srcL = reinterpret_cast<const int4*>(g_clo + nt * (128 * RS));
            int4* dstH = reinterpret_cast<int4*>(smem + SM_CH);
            int4* dstL = reinterpret_cast<int4*>(smem + SM_CL);
            for (int i = tid; i < TILE_HB / 16; i += 256) {
                dstH[i] = srcH[i];
                dstL[i] = srcL[i];
            }
        }
        __syncthreads();

        float acc[2][8][4];
        #pragma unroll
        for (int mi = 0; mi < 2; ++mi)
            #pragma unroll
            for (int nj = 0; nj < 8; ++nj)
                #pragma unroll
                for (int e = 0; e < 4; ++e) acc[mi][nj][e] = 0.0f;

        const unsigned aT[3] = {sbase + SM_FH, sbase + SM_FH, sbase + SM_FL};
        const unsigned bT[3] = {sbase + SM_CH, sbase + SM_CL, sbase + SM_CH};

        #pragma unroll
        for (int pass = 0; pass < 3; ++pass) {
            unsigned abase = aT[pass] + (unsigned)(warpM * RSB) + aOff;
            unsigned bbase = bT[pass] + (unsigned)(warpNh * 64 * RSB) + bOff;
            #pragma unroll
            for (int ks = 0; ks < 8; ++ks) {
                unsigned a0[4], a1[4];
                ldmx4(a0, abase + ks * 32);
                ldmx4(a1, abase + ks * 32 + 16 * RSB);
                unsigned b[4][4];
                #pragma unroll
                for (int f2 = 0; f2 < 4; ++f2)
                    ldmx4(b[f2], bbase + ks * 32 + f2 * 16 * RSB);
                #pragma unroll
                for (int f2 = 0; f2 < 4; ++f2) {
                    mma16816(acc[0][f2 * 2 + 0], a0, &b[f2][0]);
                    mma16816(acc[0][f2 * 2 + 1], a0, &b[f2][2]);
                    mma16816(acc[1][f2 * 2 + 0], a1, &b[f2][0]);
                    mma16816(acc[1][f2 * 2 + 1], a1, &b[f2][2]);
                }
            }
        }

        // epilogue: d2 = c2 - 2*dot, track per-lane best for the 4 rows this lane owns
        #pragma unroll
        for (int mi = 0; mi < 2; ++mi)
            #pragma unroll
            for (int nj = 0; nj < 8; ++nj) {
                int cbase = nt * 128 + warpNh * 64 + nj * 8 + 2 * (l & 3);
                float c2a = sc2s[cbase], c2b = sc2s[cbase + 1];
                #pragma unroll
                for (int pi = 0; pi < 2; ++pi) {
                    int slot = mi * 2 + pi;
                    float e0 = fmaf(-2.0f, acc[mi][nj][pi * 2 + 0], c2a);
                    float e1 = fmaf(-2.0f, acc[mi][nj][pi * 2 + 1], c2b);
                    if (e0 < best[slot]) { best[slot] = e0; bidx[slot] = cbase; }
                    if (e1 < best[slot] ||
                        (e1 == best[slot] && cbase + 1 < bidx[slot])) {
                        best[slot] = e1; bidx[slot] = cbase + 1;
                    }
                }
            }
        __syncthreads();  // before next tile's copy overwrites C smem
    }

    // reduce across the 4 lanes sharing each row group (lanes l^1, l^2)
    #pragma unroll
    for (int j = 0; j < 4; ++j) {
        float bv = best[j];
        int bi = bidx[j];
        #pragma unroll
        for (int off = 1; off <= 2; off <<= 1) {
            float ov = __shfl_xor_sync(0xFFFFFFFFu, bv, off);
            int   oi = __shfl_xor_sync(0xFFFFFFFFu, bi, off);
            if (ov < bv || (ov == bv && oi < bi)) { bv = ov; bi = oi; }
        }
        if ((l & 3) == 0) {
            int mi = j >> 1, pi = j & 1;
            int row = warpM + mi * 16 + pi * 8 + (l >> 2);
            ((float*)(smem + SM_MRG))[warpNh * 128 + row] = bv;
            ((int*)(smem + SM_MRG + 1024))[warpNh * 128 + row] = bi;
        }
    }
    __syncthreads();
    if (tid < 128) {
        float b0 = ((float*)(smem + SM_MRG))[tid];
        float b1 = ((float*)(smem + SM_MRG))[128 + tid];
        int   i0 = ((int*)(smem + SM_MRG + 1024))[tid];
        int   i1 = ((int*)(smem + SM_MRG + 1024))[128 + tid];
        int idx = (b1 < b0 || (b1 == b0 && i1 < i0)) ? i1 : i0;
        int p = pbase + tid;
        if (p < N) {
            g_assign[p] = idx;
            out_assign[p] = (float)idx;
        }
    }
}

// ---------------- accumulate: warp/point, vector red.global.add.v4 ----------------
__global__ __launch_bounds__(256)
void accum_kernel(const float* __restrict__ F, int N) {
    int warp = (blockIdx.x * blockDim.x + threadIdx.x) >> 5;
    int lane = threadIdx.x & 31;
    if (warp >= N) return;
    int a = g_assign[warp];
    float4 v = reinterpret_cast<const float4*>(F + (size_t)warp * DD)[lane];
    float* dst = g_sums + (size_t)(warp & (PARTS - 1)) * (KK * DD) + a * DD + lane * 4;
    asm volatile("red.global.add.v4.f32 [%0], {%1, %2, %3, %4};"
                 :: "l"(dst), "f"(v.x), "f"(v.y), "f"(v.z), "f"(v.w) : "memory");
    if (lane == 0) atomicAdd(&g_counts[a], 1);
}

// ---------------- finalize: merge privatized copies, divide ----------------
__global__ void finalize_kernel(float* __restrict__ out) {
    int t = blockIdx.x * blockDim.x + threadIdx.x;
    if (t >= KK * DD) return;
    float s = 0.0f;
    #pragma unroll
    for (int p = 0; p < PARTS; ++p) s += g_sums[p * KK * DD + t];
    int k = t >> 7;
    float c = fmaxf((float)g_counts[k], 1.0f);
    out[t] = s / c;
}

// ---------------- launch ----------------
extern "C" void kernel_launch(void* const* d_in, const int* in_sizes, int n_in,
                              void* d_out, int out_size) {
    const float* F = (const float*)d_in[0];
    const float* C = (const float*)d_in[1];
    if (n_in >= 2 && in_sizes[0] < in_sizes[1]) { const float* t = F; F = C; C = t; }
    int szF = in_sizes[0] > in_sizes[1] ? in_sizes[0] : in_sizes[1];
    int N = szF / DD;
    if (N > NMAX) N = NMAX;

    float* out = (float*)d_out;
    const int KD = KK * DD;
    float* out_assign = out + KD;  // harness sizes out as KD + N

    cudaFuncSetAttribute(assign_kernel, cudaFuncAttributeMaxDynamicSharedMemorySize,
                         SMEM_TOTAL);

    prep_kernel<<<(PARTS * KD + 255) / 256, 256>>>(C);
    assign_kernel<<<(N + BM - 1) / BM, 256, SMEM_TOTAL>>>(F, N, out_assign);
    accum_kernel<<<(N + 7) / 8, 256>>>(F, N);
    finalize_kernel<<<(KD + 255) / 256, 256>>>(out);
}

// round 12
// speedup vs baseline: 2.5054x; 1.0055x over previous
#include <cuda_runtime.h>
#include <cuda_fp16.h>
#include <cstdint>

// Problem constants (fixed by the reference: N=200000, D=128, K=512)
#define DD 128
#define KK 512
#define NMAX 200000
#define PARTS 8

#define BM 128            // points per CTA
#define RS 136            // padded smem row stride in fp16 elems (272B)
#define RSB 272           // row stride bytes
#define TILE_HB (128*RSB) // one 128x128 fp16 padded tile = 34816 B
#define CBUF (2*TILE_HB)  // one C buffer (hi+lo) = 69632 B

// smem offsets (bytes)
#define SM_FH  0
#define SM_FL  TILE_HB
#define SM_C0  (2*TILE_HB)            // C buffer 0 (hi at +0, lo at +TILE_HB)
#define SM_C1  (SM_C0 + CBUF)         // C buffer 1
#define SM_C2  (SM_C1 + CBUF)         // 512 floats
#define SM_MRG (SM_C2 + 2048)         // 2 x 128 (float,int)
#define SMEM_TOTAL (SM_MRG + 2048)    // 212992 B

// ---------------- scratch (no allocations allowed) ----------------
__device__ int   g_assign[NMAX];
__device__ float g_c2[KK];
__device__ float g_sums[PARTS * KK * DD];
__device__ int   g_counts[KK];
// centers as hi/lo fp16 in padded tile layout: [4 tiles][128 rows][RS]
__device__ __align__(16) unsigned short g_chi[4 * 128 * RS];
__device__ __align__(16) unsigned short g_clo[4 * 128 * RS];

__device__ __forceinline__ unsigned smem_u32(const void* p) {
    unsigned a;
    asm("{ .reg .u64 t; cvta.to.shared.u64 t, %1; cvt.u32.u64 %0, t; }" : "=r"(a) : "l"(p));
    return a;
}
__device__ __forceinline__ void ldmx4(unsigned* r, unsigned addr) {
    asm volatile("ldmatrix.sync.aligned.m8n8.x4.shared.b16 {%0,%1,%2,%3}, [%4];"
                 : "=r"(r[0]), "=r"(r[1]), "=r"(r[2]), "=r"(r[3]) : "r"(addr));
}
__device__ __forceinline__ void mma16816(float* d, const unsigned* a, const unsigned* b) {
    asm volatile("mma.sync.aligned.m16n8k16.row.col.f32.f16.f16.f32 "
                 "{%0,%1,%2,%3}, {%4,%5,%6,%7}, {%8,%9}, {%0,%1,%2,%3};"
                 : "+f"(d[0]), "+f"(d[1]), "+f"(d[2]), "+f"(d[3])
                 : "r"(a[0]), "r"(a[1]), "r"(a[2]), "r"(a[3]), "r"(b[0]), "r"(b[1]));
}

// ---------------- prep: zero sums, c2, center hi/lo images ----------------
__global__ void prep_kernel(const float* __restrict__ C) {
    int t = blockIdx.x * blockDim.x + threadIdx.x;
    if (t < PARTS * KK * DD) g_sums[t] = 0.0f;
    if (t < KK * DD) {
        int c = t >> 7, k = t & 127;
        float x = C[t];
        __half hi = __float2half_rn(x);
        __half lo = __float2half_rn(x - __half2float(hi));
        int tile = c >> 7, r = c & 127;
        int idx = tile * (128 * RS) + r * RS + k;
        g_chi[idx] = __half_as_ushort(hi);
        g_clo[idx] = __half_as_ushort(lo);
    }
    if (t < KK) {
        g_counts[t] = 0;
        const float* row = C + t * DD;
        float s = 0.0f;
        #pragma unroll 8
        for (int d = 0; d < DD; ++d) { float v = row[d]; s += v * v; }
        g_c2[t] = s;
    }
}

// ---------------- assign: HMMA fp16-split GEMM, cp.async double-buffered C ----------------
__global__ __launch_bounds__(256, 1)
void assign_kernel(const float* __restrict__ F, int N, float* __restrict__ out_assign) {
    extern __shared__ char smem[];
    const unsigned sbase = smem_u32(smem);
    const int tid = threadIdx.x;
    const int wid = tid >> 5;
    const int l = tid & 31;
    const int pbase = blockIdx.x * BM;

    const int warpM = (wid >> 1) * 32;     // point rows 0..96
    const int warpNh = wid & 1;            // n-half (0: cols 0-63, 1: 64-127)

    // issue async copy of a C tile (hi+lo) into buffer `buf`
    auto copy_tile = [&](int nt, int buf) {
        const char* srcH = (const char*)(g_chi + nt * (128 * RS));
        const char* srcL = (const char*)(g_clo + nt * (128 * RS));
        unsigned dst = sbase + SM_C0 + buf * CBUF;
        #pragma unroll
        for (int it = 0; it < 17; ++it) {
            int i = tid + it * 256;          // 0..4351 16B chunks
            const char* s;
            unsigned d;
            if (i < 2176) { s = srcH + i * 16; d = dst + i * 16; }
            else          { s = srcL + (i - 2176) * 16; d = dst + TILE_HB + (i - 2176) * 16; }
            asm volatile("cp.async.cg.shared.global [%0], [%1], 16;" :: "r"(d), "l"(s));
        }
        asm volatile("cp.async.commit_group;" ::: "memory");
    };

    // kick off tile 0 copy — overlaps with the F convert below
    copy_tile(0, 0);

    // ---- convert F block to hi/lo fp16 in padded smem ----
    #pragma unroll
    for (int it = 0; it < 16; ++it) {
        int s = tid + it * 256;            // 4096 float4 slots
        int row = s >> 5;                  // 0..127
        int q = s & 31;                    // float4 within row
        int p = pbase + row;
        float4 v = make_float4(0.f, 0.f, 0.f, 0.f);
        if (p < N) v = *reinterpret_cast<const float4*>(F + (size_t)p * DD + q * 4);
        __half h0 = __float2half_rn(v.x), h1 = __float2half_rn(v.y);
        __half h2 = __float2half_rn(v.z), h3 = __float2half_rn(v.w);
        __half l0 = __float2half_rn(v.x - __half2float(h0));
        __half l1 = __float2half_rn(v.y - __half2float(h1));
        __half l2 = __float2half_rn(v.z - __half2float(h2));
        __half l3 = __float2half_rn(v.w - __half2float(h3));
        unsigned hp0 = __half_as_ushort(h0) | ((unsigned)__half_as_ushort(h1) << 16);
        unsigned hp1 = __half_as_ushort(h2) | ((unsigned)__half_as_ushort(h3) << 16);
        unsigned lp0 = __half_as_ushort(l0) | ((unsigned)__half_as_ushort(l1) << 16);
        unsigned lp1 = __half_as_ushort(l2) | ((unsigned)__half_as_ushort(l3) << 16);
        int boff = row * RSB + q * 8;
        *reinterpret_cast<uint2*>(smem + SM_FH + boff) = make_uint2(hp0, hp1);
        *reinterpret_cast<uint2*>(smem + SM_FL + boff) = make_uint2(lp0, lp1);
    }
    // c2 -> smem
    ((float*)(smem + SM_C2))[tid]       = g_c2[tid];
    ((float*)(smem + SM_C2))[tid + 256] = g_c2[tid + 256];

    asm volatile("cp.async.wait_group 0;" ::: "memory");
    __syncthreads();

    // ldmatrix lane-relative offsets
    const unsigned aOff = (unsigned)((l & 15) * RSB + ((l >> 4) & 1) * 16);
    const unsigned bOff = (unsigned)((((l >> 4) & 1) * 8 + (l & 7)) * RSB + ((l >> 3) & 1) * 16);

    float best[4];
    int   bidx[4];
    #pragma unroll
    for (int j = 0; j < 4; ++j) { best[j] = 3.4e38f; bidx[j] = 0; }

    const float* sc2s = (const float*)(smem + SM_C2);

    #pragma unroll 1
    for (int nt = 0; nt < 4; ++nt) {
        const int buf = nt & 1;
        // prefetch next tile into the other buffer (safe: its last consumer
        // finished at the barrier that ended iteration nt-1)
        if (nt < 3) copy_tile(nt + 1, buf ^ 1);

        float acc[2][8][4];
        #pragma unroll
        for (int mi = 0; mi < 2; ++mi)
            #pragma unroll
            for (int nj = 0; nj < 8; ++nj)
                #pragma unroll
                for (int e = 0; e < 4; ++e) acc[mi][nj][e] = 0.0f;

        const unsigned cbase = sbase + SM_C0 + buf * CBUF;
        const unsigned aT[3] = {sbase + SM_FH, sbase + SM_FH, sbase + SM_FL};
        const unsigned bT[3] = {cbase, cbase + TILE_HB, cbase};

        #pragma unroll
        for (int pass = 0; pass < 3; ++pass) {
            unsigned abase = aT[pass] + (unsigned)(warpM * RSB) + aOff;
            unsigned bbase = bT[pass] + (unsigned)(warpNh * 64 * RSB) + bOff;
            #pragma unroll
            for (int ks = 0; ks < 8; ++ks) {
                unsigned a0[4], a1[4];
                ldmx4(a0, abase + ks * 32);
                ldmx4(a1, abase + ks * 32 + 16 * RSB);
                unsigned b[4][4];
                #pragma unroll
                for (int f2 = 0; f2 < 4; ++f2)
                    ldmx4(b[f2], bbase + ks * 32 + f2 * 16 * RSB);
                #pragma unroll
                for (int f2 = 0; f2 < 4; ++f2) {
                    mma16816(acc[0][f2 * 2 + 0], a0, &b[f2][0]);
                    mma16816(acc[0][f2 * 2 + 1], a0, &b[f2][2]);
                    mma16816(acc[1][f2 * 2 + 0], a1, &b[f2][0]);
                    mma16816(acc[1][f2 * 2 + 1], a1, &b[f2][2]);
                }
            }
        }

        // epilogue: d2 = c2 - 2*dot, per-lane best for the 4 rows this lane owns
        #pragma unroll
        for (int mi = 0; mi < 2; ++mi)
            #pragma unroll
            for (int nj = 0; nj < 8; ++nj) {
                int cbase2 = nt * 128 + warpNh * 64 + nj * 8 + 2 * (l & 3);
                float c2a = sc2s[cbase2], c2b = sc2s[cbase2 + 1];
                #pragma unroll
                for (int pi = 0; pi < 2; ++pi) {
                    int slot = mi * 2 + pi;
                    float e0 = fmaf(-2.0f, acc[mi][nj][pi * 2 + 0], c2a);
                    float e1 = fmaf(-2.0f, acc[mi][nj][pi * 2 + 1], c2b);
                    if (e0 < best[slot]) { best[slot] = e0; bidx[slot] = cbase2; }
                    if (e1 < best[slot] ||
                        (e1 == best[slot] && cbase2 + 1 < bidx[slot])) {
                        best[slot] = e1; bidx[slot] = cbase2 + 1;
                    }
                }
            }

        if (nt < 3) {
            asm volatile("cp.async.wait_group 0;" ::: "memory");
            __syncthreads();
        }
    }

    // reduce across the 4 lanes sharing each row group
    #pragma unroll
    for (int j = 0; j < 4; ++j) {
        float bv = best[j];
        int bi = bidx[j];
        #pragma unroll
        for (int off = 1; off <= 2; off <<= 1) {
            float ov = __shfl_xor_sync(0xFFFFFFFFu, bv, off);
            int   oi = __shfl_xor_sync(0xFFFFFFFFu, bi, off);
            if (ov < bv || (ov == bv && oi < bi)) { bv = ov; bi = oi; }
        }
        if ((l & 3) == 0) {
            int mi = j >> 1, pi = j & 1;
            int row = warpM + mi * 16 + pi * 8 + (l >> 2);
            ((float*)(smem + SM_MRG))[warpNh * 128 + row] = bv;
            ((int*)(smem + SM_MRG + 1024))[warpNh * 128 + row] = bi;
        }
    }
    __syncthreads();
    if (tid < 128) {
        float b0 = ((float*)(smem + SM_MRG))[tid];
        float b1 = ((float*)(smem + SM_MRG))[128 + tid];
        int   i0 = ((int*)(smem + SM_MRG + 1024))[tid];
        int   i1 = ((int*)(smem + SM_MRG + 1024))[128 + tid];
        int idx = (b1 < b0 || (b1 == b0 && i1 < i0)) ? i1 : i0;
        int p = pbase + tid;
        if (p < N) {
            g_assign[p] = idx;
            out_assign[p] = (float)idx;
        }
    }
}

// ---------------- accumulate: warp/point, vector red.global.add.v4 ----------------
__global__ __launch_bounds__(256)
void accum_kernel(const float* __restrict__ F, int N) {
    int warp = (blockIdx.x * blockDim.x + threadIdx.x) >> 5;
    int lane = threadIdx.x & 31;
    if (warp >= N) return;
    int a = g_assign[warp];
    float4 v = reinterpret_cast<const float4*>(F + (size_t)warp * DD)[lane];
    float* dst = g_sums + (size_t)(warp & (PARTS - 1)) * (KK * DD) + a * DD + lane * 4;
    asm volatile("red.global.add.v4.f32 [%0], {%1, %2, %3, %4};"
                 :: "l"(dst), "f"(v.x), "f"(v.y), "f"(v.z), "f"(v.w) : "memory");
    if (lane == 0) atomicAdd(&g_counts[a], 1);
}

// ---------------- finalize: merge privatized copies, divide ----------------
__global__ void finalize_kernel(float* __restrict__ out) {
    int t = blockIdx.x * blockDim.x + threadIdx.x;
    if (t >= KK * DD) return;
    float s = 0.0f;
    #pragma unroll
    for (int p = 0; p < PARTS; ++p) s += g_sums[p * KK * DD + t];
    int k = t >> 7;
    float c = fmaxf((float)g_counts[k], 1.0f);
    out[t] = s / c;
}

// ---------------- launch ----------------
extern "C" void kernel_launch(void* const* d_in, const int* in_sizes, int n_in,
                              void* d_out, int out_size) {
    const float* F = (const float*)d_in[0];
    const float* C = (const float*)d_in[1];
    if (n_in >= 2 && in_sizes[0] < in_sizes[1]) { const float* t = F; F = C; C = t; }
    int szF = in_sizes[0] > in_sizes[1] ? in_sizes[0] : in_sizes[1];
    int N = szF / DD;
    if (N > NMAX) N = NMAX;

    float* out = (float*)d_out;
    const int KD = KK * DD;
    float* out_assign = out + KD;  // harness sizes out as KD + N

    cudaFuncSetAttribute(assign_kernel, cudaFuncAttributeMaxDynamicSharedMemorySize,
                         SMEM_TOTAL);

    prep_kernel<<<(PARTS * KD + 255) / 256, 256>>>(C);
    assign_kernel<<<(N + BM - 1) / BM, 256, SMEM_TOTAL>>>(F, N, out_assign);
    accum_kernel<<<(N + 7) / 8, 256>>>(F, N);
    finalize_kernel<<<(KD + 255) / 256, 256>>>(out);
}